// round 9
// baseline (speedup 1.0000x reference)
#include <cuda_runtime.h>
#include <math.h>
#include <stdint.h>

// Problem constants
#define TT    512
#define KK    256
#define VVV   32000
#define RROWS 1024          // B*T
#define INNER 512
#define NTB   1024          // threads in final fused kernel
#define CAND_MAX 1024
#define EQ_MAX   128

// ---------------- device scratch (no allocations allowed) ----------------
__device__ float g_G   [RROWS*KK];      // gathered (pre-norm)
__device__ float g_Gn  [RROWS*KK];      // rmsnorm(gathered)
__device__ float g_QKV [3*RROWS*KK];    // Q | K | V blocks
__device__ float g_S   [2*TT*TT];       // decay-weighted scores per batch
__device__ float g_Ret [RROWS*KK];      // retrieved
__device__ float g_G2  [RROWS*KK];      // gathered + mem update
__device__ float g_G2n [RROWS*KK];      // rmsnorm of g_G2
__device__ float g_H   [RROWS*INNER];   // mlp hidden (post-gelu)
__device__ float g_OutU[RROWS*KK];      // unscaled mlp output

// ---------------- warp helpers ----------------
__device__ __forceinline__ float warpMaxF(float v){
  #pragma unroll
  for (int o=16;o;o>>=1) v = fmaxf(v, __shfl_xor_sync(0xffffffffu, v, o));
  return v;
}
__device__ __forceinline__ float warpSumF(float v){
  #pragma unroll
  for (int o=16;o;o>>=1) v += __shfl_xor_sync(0xffffffffu, v, o);
  return v;
}

// ---------------- rmsnorm kernels: one row per 256-thread block ----------------
__global__ void k_rms1(const float* __restrict__ x, const int* __restrict__ ridx){
  int row = blockIdx.x, tid = threadIdx.x;
  float v = x[(size_t)row*VVV + ridx[tid]];
  float ss = warpSumF(v*v);
  __shared__ float part[8];
  __shared__ float s_r;
  if ((tid&31)==0) part[tid>>5] = ss;
  __syncthreads();
  if (tid==0){
    float t = 0.f;
    #pragma unroll
    for (int i=0;i<8;i++) t += part[i];
    s_r = rsqrtf(t*(1.f/256.f) + 1.1920929e-07f);
  }
  __syncthreads();
  g_G [row*KK+tid] = v;
  g_Gn[row*KK+tid] = v*s_r;
}

__global__ void k_rms2(){
  int row = blockIdx.x, tid = threadIdx.x;
  float v = g_G2[row*KK+tid];
  float ss = warpSumF(v*v);
  __shared__ float part[8];
  __shared__ float s_r;
  if ((tid&31)==0) part[tid>>5] = ss;
  __syncthreads();
  if (tid==0){
    float t = 0.f;
    #pragma unroll
    for (int i=0;i<8;i++) t += part[i];
    s_r = rsqrtf(t*(1.f/256.f) + 1.1920929e-07f);
  }
  __syncthreads();
  g_G2n[row*KK+tid] = v*s_r;
}

// ---------------- generic tiled fp32 GEMM, register-prefetch pipelined ----------------
// C[M,N] = A[M,Kd] x B  (TRANSB=1: B is [N,Kd]; TRANSB=0: B is [Kd,N])
// EPI: 0 plain, 1 decay-weighted scores, 2 residual+scales, 3 bias+gelu
// QKVSEL: z selects among B0/B1/B2 (weights), C offset z*M*N
// TRIU: 1 = skip all-zero score tiles (s<=t), 2 = start k at m0 (S strict upper)
// As stored TRANSPOSED (As[k][m]) so the inner loop is 2x LDS.128 + 16 FFMA.
template<int EPI, int TRANSB, int QKVSEL, int TRIU>
__global__ void __launch_bounds__(256)
gemm_k(const float* __restrict__ A,
       const float* __restrict__ B0, const float* __restrict__ B1, const float* __restrict__ B2,
       float* __restrict__ C,
       int M, int N, int Kd,
       int sAz, int sBz, int sCz,
       const float* __restrict__ aux1,   // decay_logit (EPI1) / bias (EPI3)
       const float* __restrict__ aux2,   // mem_scale   (EPI2)
       const float* __restrict__ aux3,   // out_scale   (EPI2)
       const float* __restrict__ resid)  // residual    (EPI2)
{
  __shared__ float As[16][64];   // [k][m]  (transposed)
  __shared__ float Bs[16][64];   // [k][n]

  int z = blockIdx.z;
  const float* Ap = A + (size_t)z * sAz;
  const float* Bp;
  if (QKVSEL) Bp = (z==0) ? B0 : ((z==1) ? B1 : B2);
  else        Bp = B0 + (size_t)z * sBz;
  float*       Cp = C + (size_t)z * sCz;
  const float* Rp = (EPI==2) ? (resid + (size_t)z * sCz) : resid;

  int m0 = blockIdx.y * 64, n0 = blockIdx.x * 64;
  int tid = threadIdx.x;
  int tx = tid & 15, ty = tid >> 4;

  float acc[4][4] = {};

  bool skip_all = false;
  if (EPI==1 && TRIU==1) skip_all = (n0 + 63 <= m0);   // whole tile has zero weight

  if (!skip_all) {
    int kstart = (TRIU==2) ? m0 : 0;     // first tile with nonzero S k-range
    int la_m = tid >> 2, la_k = (tid & 3) * 4;   // A/B(T) loader: 64 rows x 4 floats
    int lb_r = tid >> 4, lb_n = (tid & 15) * 4;  // B(N) loader: 16 rows x 64 cols

    // prologue: fetch first tile into registers
    float4 a_reg = *(const float4*)&Ap[(size_t)(m0 + la_m) * Kd + kstart + la_k];
    float4 b_reg;
    if (TRANSB) b_reg = *(const float4*)&Bp[(size_t)(n0 + la_m) * Kd + kstart + la_k];
    else        b_reg = *(const float4*)&Bp[(size_t)(kstart + lb_r) * N + n0 + lb_n];

    for (int k0 = kstart; k0 < Kd; k0 += 16) {
      __syncthreads();                       // previous tile fully consumed
      // store current tile registers to smem
      As[la_k+0][la_m] = a_reg.x; As[la_k+1][la_m] = a_reg.y;
      As[la_k+2][la_m] = a_reg.z; As[la_k+3][la_m] = a_reg.w;
      if (TRANSB) {
        Bs[la_k+0][la_m] = b_reg.x; Bs[la_k+1][la_m] = b_reg.y;
        Bs[la_k+2][la_m] = b_reg.z; Bs[la_k+3][la_m] = b_reg.w;
      } else {
        *(float4*)&Bs[lb_r][lb_n] = b_reg;
      }
      __syncthreads();
      // prefetch next tile (in flight during compute)
      int kn = k0 + 16;
      if (kn < Kd) {
        a_reg = *(const float4*)&Ap[(size_t)(m0 + la_m) * Kd + kn + la_k];
        if (TRANSB) b_reg = *(const float4*)&Bp[(size_t)(n0 + la_m) * Kd + kn + la_k];
        else        b_reg = *(const float4*)&Bp[(size_t)(kn + lb_r) * N + n0 + lb_n];
      }
      #pragma unroll
      for (int k = 0; k < 16; ++k) {
        float4 a4 = *(float4*)&As[k][ty*4];
        float4 b4 = *(float4*)&Bs[k][tx*4];
        acc[0][0] += a4.x*b4.x; acc[0][1] += a4.x*b4.y; acc[0][2] += a4.x*b4.z; acc[0][3] += a4.x*b4.w;
        acc[1][0] += a4.y*b4.x; acc[1][1] += a4.y*b4.y; acc[1][2] += a4.y*b4.z; acc[1][3] += a4.y*b4.w;
        acc[2][0] += a4.z*b4.x; acc[2][1] += a4.z*b4.y; acc[2][2] += a4.z*b4.z; acc[2][3] += a4.z*b4.w;
        acc[3][0] += a4.w*b4.x; acc[3][1] += a4.w*b4.y; acc[3][2] += a4.w*b4.z; acc[3][3] += a4.w*b4.w;
      }
    }
  }

  int row = m0 + ty*4;
  int col = n0 + tx*4;

  if (EPI == 0) {
    #pragma unroll
    for (int i=0;i<4;i++) {
      float4 vv = make_float4(acc[i][0],acc[i][1],acc[i][2],acc[i][3]);
      *(float4*)&Cp[(size_t)(row+i)*N + col] = vv;
    }
  } else if (EPI == 1) {
    float dl = aux1[0];
    float decay = 1.f/(1.f + expf(-dl));
    float l2d = log2f(decay);
    const float sc = 0.0625f;  // 1/sqrt(256)
    #pragma unroll
    for (int i=0;i<4;i++) {
      float4 vv;
      float* pv = (float*)&vv;
      #pragma unroll
      for (int j=0;j<4;j++) {
        int t = row+i, s_ = col+j;
        float w = 0.f;
        if (s_ > t) w = exp2f((float)(s_ - t - 1) * l2d);
        pv[j] = acc[i][j] * sc * w;
      }
      *(float4*)&Cp[(size_t)(row+i)*N + col] = vv;
    }
  } else if (EPI == 2) {
    float msv = aux2[0] * aux3[0];
    #pragma unroll
    for (int i=0;i<4;i++) {
      float4 rr = *(const float4*)&Rp[(size_t)(row+i)*N + col];
      float4 vv = make_float4(rr.x + msv*acc[i][0], rr.y + msv*acc[i][1],
                              rr.z + msv*acc[i][2], rr.w + msv*acc[i][3]);
      *(float4*)&Cp[(size_t)(row+i)*N + col] = vv;
    }
  } else { // EPI == 3: bias + exact gelu
    #pragma unroll
    for (int i=0;i<4;i++) {
      float4 vv;
      float* pv = (float*)&vv;
      #pragma unroll
      for (int j=0;j<4;j++) {
        float h = acc[i][j] + aux1[col+j];
        pv[j] = 0.5f * h * (1.f + erff(h * 0.70710678118654752f));
      }
      *(float4*)&Cp[(size_t)(row+i)*N + col] = vv;
    }
  }
}

// ---------------- fused entropy + delta + exact top-128 + masked write ----------------
__global__ void __launch_bounds__(NTB)
k_final(const float* __restrict__ x,
        const float* __restrict__ outU,
        const int*   __restrict__ widx,
        const float* __restrict__ p_ws,
        float* __restrict__ out)
{
  extern __shared__ float s[];            // 32000 floats = this row
  __shared__ float    sredA[33];
  __shared__ float    sredB[33];
  __shared__ int      sredI[33];
  __shared__ unsigned s_cand[CAND_MAX];
  __shared__ int      s_eqidx[EQ_MAX];
  __shared__ int      s_cnt;
  __shared__ int      s_eqcnt;
  __shared__ int      s_ngt;
  __shared__ unsigned s_u;

  int row = blockIdx.x;
  int tid = threadIdx.x;
  int lane = tid & 31, wid = tid >> 5;
  const float4* xin = (const float4*)(x + (size_t)row * VVV);
  float4*       o4  = (float4*)(out + (size_t)row * VVV);
  float4*       s4  = (float4*)s;

  // ---- pass 1: load row to smem, compute max ----
  float mx = -3.402823466e+38f;
  #pragma unroll 4
  for (int i = tid; i < VVV/4; i += NTB) {
    float4 v = xin[i];
    s4[i] = v;
    mx = fmaxf(mx, fmaxf(fmaxf(v.x, v.y), fmaxf(v.z, v.w)));
  }
  { // block max -> all
    float wv = warpMaxF(mx);
    if (lane==0) sredA[wid] = wv;
    __syncthreads();
    if (tid==0){
      float m = sredA[0];
      #pragma unroll
      for (int i=1;i<32;i++) m = fmaxf(m, sredA[i]);
      sredA[32] = m;
    }
    __syncthreads();
  }
  float m = sredA[32];

  // ---- pass 2: S0 = sum e^{x-m}, S1 = sum (x-m) e^{x-m} ----
  float S0 = 0.f, S1 = 0.f;
  #pragma unroll 4
  for (int i = tid; i < VVV; i += NTB) {
    float v = s[i] - m;
    float e = __expf(v);
    S0 += e; S1 += v * e;
  }
  {
    float w0 = warpSumF(S0), w1 = warpSumF(S1);
    if (lane==0){ sredA[wid]=w0; sredB[wid]=w1; }
    __syncthreads();
    if (tid==0){
      float t0=0.f, t1=0.f;
      #pragma unroll
      for (int i=0;i<32;i++){ t0+=sredA[i]; t1+=sredB[i]; }
      sredA[32]=t0; sredB[32]=t1;
      s_cnt = 0;                       // init for fused count+collect below
    }
    __syncthreads();
  }
  // H_ref = -sum p*log(p+1e-8) = [log S0 - S1/S0] - V*1e-8 + O(1e-7)
  float entropy = logf(sredA[32]) - sredB[32]/sredA[32] - 3.2e-4f;
  float scale_row = p_ws[0] * 0.0625f * (entropy * (1.0f/10.373491181781864f));

  // ---- apply delta (write positions only; indices are distinct) ----
  if (tid < KK) {
    int c = widx[tid];
    atomicAdd(&s[c], outU[(size_t)row*KK + tid] * scale_row);
  }
  __syncthreads();

  // ---- fused count + collect at initial pivot (expected ~300 cands) ----
  float pivot = 2.6f;
  unsigned pb = __float_as_uint(pivot);
  for (int i = tid; i < VVV; i += NTB) {
    unsigned kb = __float_as_uint(s[i]) & 0x7fffffffu;
    if (kb >= pb) {
      int p = atomicAdd(&s_cnt, 1);
      if (p < CAND_MAX) s_cand[p] = kb;
    }
  }
  __syncthreads();
  int c = s_cnt;

  if (c < 128 || c > CAND_MAX) {
    // ---- adaptive pivot: count-only until count lands in [128, CAND_MAX] ----
    for (int it = 0; it < 32; ++it) {
      pivot = (c < 128) ? pivot * 0.70f : pivot * 1.35f;
      pb = __float_as_uint(pivot);
      int lc = 0;
      for (int i = tid; i < VVV; i += NTB) {
        unsigned kb = __float_as_uint(s[i]) & 0x7fffffffu;
        lc += (kb >= pb);
      }
      int wv = __reduce_add_sync(0xffffffffu, lc);
      __syncthreads();
      if (lane==0) sredI[wid] = wv;
      __syncthreads();
      if (tid==0){
        int t=0;
        #pragma unroll
        for (int i=0;i<32;i++) t += sredI[i];
        sredI[32]=t;
      }
      __syncthreads();
      c = sredI[32];
      if (c >= 128 && c <= CAND_MAX) break;
    }
    // recollect at accepted pivot
    if (tid==0) s_cnt = 0;
    __syncthreads();
    for (int i = tid; i < VVV; i += NTB) {
      unsigned kb = __float_as_uint(s[i]) & 0x7fffffffu;
      if (kb >= pb) {
        int p = atomicAdd(&s_cnt, 1);
        if (p < CAND_MAX) s_cand[p] = kb;
      }
    }
    __syncthreads();
    c = min(s_cnt, CAND_MAX);
  }

  // zero-pad candidate array
  for (int i = c + tid; i < CAND_MAX; i += NTB) s_cand[i] = 0u;
  __syncthreads();

  // ---- warp 0: exact 128th-largest key via greedy bit search; also n_gt ----
  if (tid < 32) {
    unsigned kr[32];
    #pragma unroll
    for (int i=0;i<32;i++) kr[i] = s_cand[tid + i*32];
    unsigned u = 0u;
    #pragma unroll 1
    for (int b = 30; b >= 0; --b) {
      unsigned candU = u | (1u << b);
      int lc = 0;
      #pragma unroll
      for (int i=0;i<32;i++) lc += (kr[i] >= candU);
      int tot = __reduce_add_sync(0xffffffffu, lc);
      if (tot >= 128) u = candU;
    }
    int gt = 0;
    #pragma unroll
    for (int i=0;i<32;i++) gt += (kr[i] > u);
    gt = __reduce_add_sync(0xffffffffu, gt);
    if (tid==0){ s_u = u; s_ngt = gt; s_eqcnt = 0; }
  }
  __syncthreads();
  unsigned u = s_u;

  // ---- collect indices of elements exactly equal to the threshold key ----
  for (int i = tid; i < VVV; i += NTB) {
    unsigned kb = __float_as_uint(s[i]) & 0x7fffffffu;
    if (kb == u) {
      int p = atomicAdd(&s_eqcnt, 1);
      if (p < EQ_MAX) s_eqidx[p] = i;
    }
  }
  __syncthreads();
  int neq = min(s_eqcnt, EQ_MAX);
  int extra = 128 - s_ngt;           // how many ==u elements to keep
  if (extra < 0)   extra = 0;        // safety clamp (cannot occur on expected path)
  if (extra > neq) extra = neq;

  // ---- masked write: keep key > u, plus the `extra` lowest-indexed ==u ----
  #pragma unroll 4
  for (int i = tid; i < VVV/4; i += NTB) {
    float4 v = s4[i];
    int base = i * 4;
    float* pv = (float*)&v;
    #pragma unroll
    for (int c_ = 0; c_ < 4; ++c_) {
      unsigned kb = __float_as_uint(pv[c_]) & 0x7fffffffu;
      bool keep = (kb > u);
      if (kb == u) {
        int r = 0;
        for (int j = 0; j < neq; ++j) r += (s_eqidx[j] < base + c_);
        keep = (r < extra);           // lowest-index-first, exactly top_k's tie rule
      }
      pv[c_] = keep ? pv[c_] : 0.f;
    }
    o4[i] = v;
  }
}

// ---------------- host ----------------
extern "C" void kernel_launch(void* const* d_in, const int* in_sizes, int n_in,
                              void* d_out, int out_size)
{
  const float* x        = (const float*)d_in[0];
  const float* Wq       = (const float*)d_in[1];
  const float* Wk       = (const float*)d_in[2];
  const float* Wv       = (const float*)d_in[3];
  const float* Wo       = (const float*)d_in[4];
  const float* dlogit   = (const float*)d_in[5];
  const float* oscale   = (const float*)d_in[6];
  const float* mscale   = (const float*)d_in[7];
  const float* wscale   = (const float*)d_in[8];
  const float* Wdown    = (const float*)d_in[9];
  const float* Wup      = (const float*)d_in[10];
  const float* mbias    = (const float*)d_in[11];
  const int*   ridx     = (const int*)d_in[12];
  const int*   widx     = (const int*)d_in[13];
  float*       out      = (float*)d_out;

  float *pG,*pGn,*pQKV,*pS,*pRet,*pG2,*pG2n,*pH,*pOutU;
  cudaGetSymbolAddress((void**)&pG,    g_G);
  cudaGetSymbolAddress((void**)&pGn,   g_Gn);
  cudaGetSymbolAddress((void**)&pQKV,  g_QKV);
  cudaGetSymbolAddress((void**)&pS,    g_S);
  cudaGetSymbolAddress((void**)&pRet,  g_Ret);
  cudaGetSymbolAddress((void**)&pG2,   g_G2);
  cudaGetSymbolAddress((void**)&pG2n,  g_G2n);
  cudaGetSymbolAddress((void**)&pH,    g_H);
  cudaGetSymbolAddress((void**)&pOutU, g_OutU);

  // 1) gather + rmsnorm
  k_rms1<<<RROWS, 256>>>(x, ridx);

  // 2) Q,K,V = Gn @ W{q,k,v}.T  (z selects weight)
  gemm_k<0,1,1,0><<<dim3(4,16,3), 256>>>(pGn, Wq, Wk, Wv, pQKV,
      RROWS, KK, KK, 0, 0, RROWS*KK, nullptr, nullptr, nullptr, nullptr);

  // 3) scores (decay-weighted, strictly upper): per batch
  gemm_k<1,1,0,1><<<dim3(8,8,2), 256>>>(pQKV, pQKV + RROWS*KK, nullptr, nullptr, pS,
      TT, TT, KK, TT*KK, TT*KK, TT*TT, dlogit, nullptr, nullptr, nullptr);

  // 4) retrieved = S @ V  (k starts at m0: S strict upper)
  gemm_k<0,0,0,2><<<dim3(4,8,2), 256>>>(pS, pQKV + 2*RROWS*KK, nullptr, nullptr, pRet,
      TT, KK, TT, TT*TT, TT*KK, TT*KK, nullptr, nullptr, nullptr, nullptr);

  // 5) G2 = G + mem_scale*out_scale*(Ret @ Wo.T)
  gemm_k<2,1,0,0><<<dim3(4,16,1), 256>>>(pRet, Wo, nullptr, nullptr, pG2,
      RROWS, KK, KK, 0, 0, 0, nullptr, mscale, oscale, pG);

  // 6) rmsnorm
  k_rms2<<<RROWS, 256>>>();

  // 7) H = gelu(G2n @ Wdown.T + bias)
  gemm_k<3,1,0,0><<<dim3(8,16,1), 256>>>(pG2n, Wdown, nullptr, nullptr, pH,
      RROWS, INNER, KK, 0, 0, 0, mbias, nullptr, nullptr, nullptr);

  // 8) OutU = H @ Wup.T
  gemm_k<0,1,0,0><<<dim3(4,16,1), 256>>>(pH, Wup, nullptr, nullptr, pOutU,
      RROWS, KK, INNER, 0, 0, 0, nullptr, nullptr, nullptr, nullptr);

  // 9) fused entropy + delta + exact top-128 + masked write
  cudaFuncSetAttribute(k_final, cudaFuncAttributeMaxDynamicSharedMemorySize, VVV*4);
  k_final<<<RROWS, NTB, VVV*4>>>(x, pOutU, widx, wscale, out);
}

// round 17
// speedup vs baseline: 1.0095x; 1.0095x over previous
#include <cuda_runtime.h>
#include <math.h>
#include <stdint.h>

// Problem constants
#define TT    512
#define KK    256
#define VVV   32000
#define RROWS 1024          // B*T
#define INNER 512
#define NTB   1024          // threads in final fused kernel
#define CAND_MAX 1024
#define EQ_MAX   128

// ---------------- device scratch (no allocations allowed) ----------------
__device__ float g_G   [RROWS*KK];      // gathered (pre-norm)
__device__ float g_Gn  [RROWS*KK];      // rmsnorm(gathered)
__device__ float g_QKV [3*RROWS*KK];    // Q | K | V blocks
__device__ float g_S   [2*TT*TT];       // decay-weighted scores per batch
__device__ float g_Ret [RROWS*KK];      // retrieved
__device__ float g_G2  [RROWS*KK];      // gathered + mem update
__device__ float g_G2n [RROWS*KK];      // rmsnorm of g_G2
__device__ float g_H   [RROWS*INNER];   // mlp hidden (post-gelu)
__device__ float g_OutU[RROWS*KK];      // unscaled mlp output

// ---------------- warp helpers ----------------
__device__ __forceinline__ float warpMaxF(float v){
  #pragma unroll
  for (int o=16;o;o>>=1) v = fmaxf(v, __shfl_xor_sync(0xffffffffu, v, o));
  return v;
}
__device__ __forceinline__ float warpSumF(float v){
  #pragma unroll
  for (int o=16;o;o>>=1) v += __shfl_xor_sync(0xffffffffu, v, o);
  return v;
}

// ---------------- rmsnorm kernels: one row per 256-thread block ----------------
__global__ void k_rms1(const float* __restrict__ x, const int* __restrict__ ridx){
  int row = blockIdx.x, tid = threadIdx.x;
  float v = x[(size_t)row*VVV + ridx[tid]];
  float ss = warpSumF(v*v);
  __shared__ float part[8];
  __shared__ float s_r;
  if ((tid&31)==0) part[tid>>5] = ss;
  __syncthreads();
  if (tid==0){
    float t = 0.f;
    #pragma unroll
    for (int i=0;i<8;i++) t += part[i];
    s_r = rsqrtf(t*(1.f/256.f) + 1.1920929e-07f);
  }
  __syncthreads();
  g_G [row*KK+tid] = v;
  g_Gn[row*KK+tid] = v*s_r;
}

__global__ void k_rms2(){
  int row = blockIdx.x, tid = threadIdx.x;
  float v = g_G2[row*KK+tid];
  float ss = warpSumF(v*v);
  __shared__ float part[8];
  __shared__ float s_r;
  if ((tid&31)==0) part[tid>>5] = ss;
  __syncthreads();
  if (tid==0){
    float t = 0.f;
    #pragma unroll
    for (int i=0;i<8;i++) t += part[i];
    s_r = rsqrtf(t*(1.f/256.f) + 1.1920929e-07f);
  }
  __syncthreads();
  g_G2n[row*KK+tid] = v*s_r;
}

// ---------------- tiled fp32 GEMM: BM=32, BN=64, BK=16, 256 thr, 2x4 acc ----------------
// C[M,N] = A[M,Kd] x B  (TRANSB=1: B is [N,Kd]; TRANSB=0: B is [Kd,N])
// EPI: 0 plain, 1 decay-weighted scores, 2 residual+scales, 3 bias+gelu
// QKVSEL: z selects among B0/B1/B2 (weights), C offset z*M*N
// TRIU: 1 = skip all-zero score tiles (s<=t), 2 = start k at m0 (S strict upper)
// As stored TRANSPOSED (As[k][m]) with EVEN padding (34) so float2 LDS stays
// 8-byte aligned for all k (33 made odd-k rows misaligned -> HW trap).
template<int EPI, int TRANSB, int QKVSEL, int TRIU>
__global__ void __launch_bounds__(256)
gemm_k(const float* __restrict__ A,
       const float* __restrict__ B0, const float* __restrict__ B1, const float* __restrict__ B2,
       float* __restrict__ C,
       int M, int N, int Kd,
       int sAz, int sBz, int sCz,
       const float* __restrict__ aux1,   // decay_logit (EPI1) / bias (EPI3)
       const float* __restrict__ aux2,   // mem_scale   (EPI2)
       const float* __restrict__ aux3,   // out_scale   (EPI2)
       const float* __restrict__ resid)  // residual    (EPI2)
{
  __shared__ float As[16][34];   // [k][m], EVEN pad: float2-aligned + conflict-free STS
  __shared__ float Bs[16][64];   // [k][n]

  int z = blockIdx.z;
  const float* Ap = A + (size_t)z * sAz;
  const float* Bp;
  if (QKVSEL) Bp = (z==0) ? B0 : ((z==1) ? B1 : B2);
  else        Bp = B0 + (size_t)z * sBz;
  float*       Cp = C + (size_t)z * sCz;
  const float* Rp = (EPI==2) ? (resid + (size_t)z * sCz) : resid;

  int m0 = blockIdx.y * 32, n0 = blockIdx.x * 64;
  int tid = threadIdx.x;
  int tx = tid & 15, ty = tid >> 4;     // tx: 16 n-groups of 4, ty: 16 m-groups of 2

  float acc[2][4] = {};

  bool skip_all = false;
  if (EPI==1 && TRIU==1) skip_all = (n0 + 63 <= m0);   // whole tile has zero weight

  if (!skip_all) {
    int kstart = (TRIU==2) ? m0 : 0;     // first tile with nonzero S k-range
    // A loader: 32 rows x 16 k, float2 each (256 thr x 2 floats)
    int la_m = tid >> 3, la_k = (tid & 7) * 2;
    // B loaders
    int lbt_n = tid >> 2, lbt_k = (tid & 3) * 4;   // TRANSB=1: 64 rows(N) x 16 k, float4
    int lb_r  = tid >> 4, lb_n  = (tid & 15) * 4;  // TRANSB=0: 16 rows(K) x 64 n, float4

    // prologue: fetch first tile into registers
    float2 a_reg = *(const float2*)&Ap[(size_t)(m0 + la_m) * Kd + kstart + la_k];
    float4 b_reg;
    if (TRANSB) b_reg = *(const float4*)&Bp[(size_t)(n0 + lbt_n) * Kd + kstart + lbt_k];
    else        b_reg = *(const float4*)&Bp[(size_t)(kstart + lb_r) * N + n0 + lb_n];

    for (int k0 = kstart; k0 < Kd; k0 += 16) {
      __syncthreads();                       // previous tile fully consumed
      // store current tile registers to smem (A transposed)
      As[la_k+0][la_m] = a_reg.x; As[la_k+1][la_m] = a_reg.y;
      if (TRANSB) {
        Bs[lbt_k+0][lbt_n] = b_reg.x; Bs[lbt_k+1][lbt_n] = b_reg.y;
        Bs[lbt_k+2][lbt_n] = b_reg.z; Bs[lbt_k+3][lbt_n] = b_reg.w;
      } else {
        *(float4*)&Bs[lb_r][lb_n] = b_reg;
      }
      __syncthreads();
      // prefetch next tile (in flight during compute)
      int kn = k0 + 16;
      if (kn < Kd) {
        a_reg = *(const float2*)&Ap[(size_t)(m0 + la_m) * Kd + kn + la_k];
        if (TRANSB) b_reg = *(const float4*)&Bp[(size_t)(n0 + lbt_n) * Kd + kn + lbt_k];
        else        b_reg = *(const float4*)&Bp[(size_t)(kn + lb_r) * N + n0 + lb_n];
      }
      #pragma unroll
      for (int k = 0; k < 16; ++k) {
        float2 a2 = *(float2*)&As[k][ty*2];
        float4 b4 = *(float4*)&Bs[k][tx*4];
        acc[0][0] += a2.x*b4.x; acc[0][1] += a2.x*b4.y; acc[0][2] += a2.x*b4.z; acc[0][3] += a2.x*b4.w;
        acc[1][0] += a2.y*b4.x; acc[1][1] += a2.y*b4.y; acc[1][2] += a2.y*b4.z; acc[1][3] += a2.y*b4.w;
      }
    }
  }

  int row = m0 + ty*2;
  int col = n0 + tx*4;

  if (EPI == 0) {
    #pragma unroll
    for (int i=0;i<2;i++) {
      float4 vv = make_float4(acc[i][0],acc[i][1],acc[i][2],acc[i][3]);
      *(float4*)&Cp[(size_t)(row+i)*N + col] = vv;
    }
  } else if (EPI == 1) {
    float dl = aux1[0];
    float decay = 1.f/(1.f + expf(-dl));
    float l2d = log2f(decay);
    const float sc = 0.0625f;  // 1/sqrt(256)
    #pragma unroll
    for (int i=0;i<2;i++) {
      float4 vv;
      float* pv = (float*)&vv;
      #pragma unroll
      for (int j=0;j<4;j++) {
        int t = row+i, s_ = col+j;
        float w = 0.f;
        if (s_ > t) w = exp2f((float)(s_ - t - 1) * l2d);
        pv[j] = acc[i][j] * sc * w;
      }
      *(float4*)&Cp[(size_t)(row+i)*N + col] = vv;
    }
  } else if (EPI == 2) {
    float msv = aux2[0] * aux3[0];
    #pragma unroll
    for (int i=0;i<2;i++) {
      float4 rr = *(const float4*)&Rp[(size_t)(row+i)*N + col];
      float4 vv = make_float4(rr.x + msv*acc[i][0], rr.y + msv*acc[i][1],
                              rr.z + msv*acc[i][2], rr.w + msv*acc[i][3]);
      *(float4*)&Cp[(size_t)(row+i)*N + col] = vv;
    }
  } else { // EPI == 3: bias + exact gelu
    #pragma unroll
    for (int i=0;i<2;i++) {
      float4 vv;
      float* pv = (float*)&vv;
      #pragma unroll
      for (int j=0;j<4;j++) {
        float h = acc[i][j] + aux1[col+j];
        pv[j] = 0.5f * h * (1.f + erff(h * 0.70710678118654752f));
      }
      *(float4*)&Cp[(size_t)(row+i)*N + col] = vv;
    }
  }
}

// ---------------- fused entropy + delta + exact top-128 + masked write ----------------
__global__ void __launch_bounds__(NTB)
k_final(const float* __restrict__ x,
        const float* __restrict__ outU,
        const int*   __restrict__ widx,
        const float* __restrict__ p_ws,
        float* __restrict__ out)
{
  extern __shared__ float s[];            // 32000 floats = this row
  __shared__ float    sredA[33];
  __shared__ float    sredB[33];
  __shared__ int      sredI[33];
  __shared__ unsigned s_cand[CAND_MAX];
  __shared__ int      s_eqidx[EQ_MAX];
  __shared__ int      s_cnt;
  __shared__ int      s_eqcnt;
  __shared__ int      s_ngt;
  __shared__ unsigned s_u;

  int row = blockIdx.x;
  int tid = threadIdx.x;
  int lane = tid & 31, wid = tid >> 5;
  const float4* xin = (const float4*)(x + (size_t)row * VVV);
  float4*       o4  = (float4*)(out + (size_t)row * VVV);
  float4*       s4  = (float4*)s;

  // ---- pass 1: load row to smem, compute max ----
  float mx = -3.402823466e+38f;
  #pragma unroll 4
  for (int i = tid; i < VVV/4; i += NTB) {
    float4 v = xin[i];
    s4[i] = v;
    mx = fmaxf(mx, fmaxf(fmaxf(v.x, v.y), fmaxf(v.z, v.w)));
  }
  { // block max -> all
    float wv = warpMaxF(mx);
    if (lane==0) sredA[wid] = wv;
    __syncthreads();
    if (tid==0){
      float m = sredA[0];
      #pragma unroll
      for (int i=1;i<32;i++) m = fmaxf(m, sredA[i]);
      sredA[32] = m;
    }
    __syncthreads();
  }
  float m = sredA[32];

  // ---- pass 2: S0 = sum e^{x-m}, S1 = sum (x-m) e^{x-m} ----
  float S0 = 0.f, S1 = 0.f;
  #pragma unroll 4
  for (int i = tid; i < VVV; i += NTB) {
    float v = s[i] - m;
    float e = __expf(v);
    S0 += e; S1 += v * e;
  }
  {
    float w0 = warpSumF(S0), w1 = warpSumF(S1);
    if (lane==0){ sredA[wid]=w0; sredB[wid]=w1; }
    __syncthreads();
    if (tid==0){
      float t0=0.f, t1=0.f;
      #pragma unroll
      for (int i=0;i<32;i++){ t0+=sredA[i]; t1+=sredB[i]; }
      sredA[32]=t0; sredB[32]=t1;
      s_cnt = 0;                       // init for fused count+collect below
    }
    __syncthreads();
  }
  // H_ref = -sum p*log(p+1e-8) = [log S0 - S1/S0] - V*1e-8 + O(1e-7)
  float entropy = logf(sredA[32]) - sredB[32]/sredA[32] - 3.2e-4f;
  float scale_row = p_ws[0] * 0.0625f * (entropy * (1.0f/10.373491181781864f));

  // ---- apply delta (write positions only; indices are distinct) ----
  if (tid < KK) {
    int c = widx[tid];
    atomicAdd(&s[c], outU[(size_t)row*KK + tid] * scale_row);
  }
  __syncthreads();

  // ---- fused count + collect at initial pivot (expected ~300 cands) ----
  float pivot = 2.6f;
  unsigned pb = __float_as_uint(pivot);
  for (int i = tid; i < VVV; i += NTB) {
    unsigned kb = __float_as_uint(s[i]) & 0x7fffffffu;
    if (kb >= pb) {
      int p = atomicAdd(&s_cnt, 1);
      if (p < CAND_MAX) s_cand[p] = kb;
    }
  }
  __syncthreads();
  int c = s_cnt;

  if (c < 128 || c > CAND_MAX) {
    // ---- adaptive pivot: count-only until count lands in [128, CAND_MAX] ----
    for (int it = 0; it < 32; ++it) {
      pivot = (c < 128) ? pivot * 0.70f : pivot * 1.35f;
      pb = __float_as_uint(pivot);
      int lc = 0;
      for (int i = tid; i < VVV; i += NTB) {
        unsigned kb = __float_as_uint(s[i]) & 0x7fffffffu;
        lc += (kb >= pb);
      }
      int wv = __reduce_add_sync(0xffffffffu, lc);
      __syncthreads();
      if (lane==0) sredI[wid] = wv;
      __syncthreads();
      if (tid==0){
        int t=0;
        #pragma unroll
        for (int i=0;i<32;i++) t += sredI[i];
        sredI[32]=t;
      }
      __syncthreads();
      c = sredI[32];
      if (c >= 128 && c <= CAND_MAX) break;
    }
    // recollect at accepted pivot
    if (tid==0) s_cnt = 0;
    __syncthreads();
    for (int i = tid; i < VVV; i += NTB) {
      unsigned kb = __float_as_uint(s[i]) & 0x7fffffffu;
      if (kb >= pb) {
        int p = atomicAdd(&s_cnt, 1);
        if (p < CAND_MAX) s_cand[p] = kb;
      }
    }
    __syncthreads();
    c = min(s_cnt, CAND_MAX);
  }

  // zero-pad candidate array
  for (int i = c + tid; i < CAND_MAX; i += NTB) s_cand[i] = 0u;
  __syncthreads();

  // ---- warp 0: exact 128th-largest key via greedy bit search; also n_gt ----
  if (tid < 32) {
    unsigned kr[32];
    #pragma unroll
    for (int i=0;i<32;i++) kr[i] = s_cand[tid + i*32];
    unsigned u = 0u;
    #pragma unroll 1
    for (int b = 30; b >= 0; --b) {
      unsigned candU = u | (1u << b);
      int lc = 0;
      #pragma unroll
      for (int i=0;i<32;i++) lc += (kr[i] >= candU);
      int tot = __reduce_add_sync(0xffffffffu, lc);
      if (tot >= 128) u = candU;
    }
    int gt = 0;
    #pragma unroll
    for (int i=0;i<32;i++) gt += (kr[i] > u);
    gt = __reduce_add_sync(0xffffffffu, gt);
    if (tid==0){ s_u = u; s_ngt = gt; s_eqcnt = 0; }
  }
  __syncthreads();
  unsigned u = s_u;

  // ---- collect indices of elements exactly equal to the threshold key ----
  for (int i = tid; i < VVV; i += NTB) {
    unsigned kb = __float_as_uint(s[i]) & 0x7fffffffu;
    if (kb == u) {
      int p = atomicAdd(&s_eqcnt, 1);
      if (p < EQ_MAX) s_eqidx[p] = i;
    }
  }
  __syncthreads();
  int neq = min(s_eqcnt, EQ_MAX);
  int extra = 128 - s_ngt;           // how many ==u elements to keep
  if (extra < 0)   extra = 0;        // safety clamp (cannot occur on expected path)
  if (extra > neq) extra = neq;

  // ---- masked write: keep key > u, plus the `extra` lowest-indexed ==u ----
  #pragma unroll 4
  for (int i = tid; i < VVV/4; i += NTB) {
    float4 v = s4[i];
    int base = i * 4;
    float* pv = (float*)&v;
    #pragma unroll
    for (int c_ = 0; c_ < 4; ++c_) {
      unsigned kb = __float_as_uint(pv[c_]) & 0x7fffffffu;
      bool keep = (kb > u);
      if (kb == u) {
        int r = 0;
        for (int j = 0; j < neq; ++j) r += (s_eqidx[j] < base + c_);
        keep = (r < extra);           // lowest-index-first, exactly top_k's tie rule
      }
      pv[c_] = keep ? pv[c_] : 0.f;
    }
    o4[i] = v;
  }
}

// ---------------- host ----------------
extern "C" void kernel_launch(void* const* d_in, const int* in_sizes, int n_in,
                              void* d_out, int out_size)
{
  const float* x        = (const float*)d_in[0];
  const float* Wq       = (const float*)d_in[1];
  const float* Wk       = (const float*)d_in[2];
  const float* Wv       = (const float*)d_in[3];
  const float* Wo       = (const float*)d_in[4];
  const float* dlogit   = (const float*)d_in[5];
  const float* oscale   = (const float*)d_in[6];
  const float* mscale   = (const float*)d_in[7];
  const float* wscale   = (const float*)d_in[8];
  const float* Wdown    = (const float*)d_in[9];
  const float* Wup      = (const float*)d_in[10];
  const float* mbias    = (const float*)d_in[11];
  const int*   ridx     = (const int*)d_in[12];
  const int*   widx     = (const int*)d_in[13];
  float*       out      = (float*)d_out;

  float *pG,*pGn,*pQKV,*pS,*pRet,*pG2,*pG2n,*pH,*pOutU;
  cudaGetSymbolAddress((void**)&pG,    g_G);
  cudaGetSymbolAddress((void**)&pGn,   g_Gn);
  cudaGetSymbolAddress((void**)&pQKV,  g_QKV);
  cudaGetSymbolAddress((void**)&pS,    g_S);
  cudaGetSymbolAddress((void**)&pRet,  g_Ret);
  cudaGetSymbolAddress((void**)&pG2,   g_G2);
  cudaGetSymbolAddress((void**)&pG2n,  g_G2n);
  cudaGetSymbolAddress((void**)&pH,    g_H);
  cudaGetSymbolAddress((void**)&pOutU, g_OutU);

  // 1) gather + rmsnorm
  k_rms1<<<RROWS, 256>>>(x, ridx);

  // 2) Q,K,V = Gn @ W{q,k,v}.T  (z selects weight)
  gemm_k<0,1,1,0><<<dim3(4,32,3), 256>>>(pGn, Wq, Wk, Wv, pQKV,
      RROWS, KK, KK, 0, 0, RROWS*KK, nullptr, nullptr, nullptr, nullptr);

  // 3) scores (decay-weighted, strictly upper): per batch
  gemm_k<1,1,0,1><<<dim3(8,16,2), 256>>>(pQKV, pQKV + RROWS*KK, nullptr, nullptr, pS,
      TT, TT, KK, TT*KK, TT*KK, TT*TT, dlogit, nullptr, nullptr, nullptr);

  // 4) retrieved = S @ V  (k starts at m0: S strict upper)
  gemm_k<0,0,0,2><<<dim3(4,16,2), 256>>>(pS, pQKV + 2*RROWS*KK, nullptr, nullptr, pRet,
      TT, KK, TT, TT*TT, TT*KK, TT*KK, nullptr, nullptr, nullptr, nullptr);

  // 5) G2 = G + mem_scale*out_scale*(Ret @ Wo.T)
  gemm_k<2,1,0,0><<<dim3(4,32,1), 256>>>(pRet, Wo, nullptr, nullptr, pG2,
      RROWS, KK, KK, 0, 0, 0, nullptr, mscale, oscale, pG);

  // 6) rmsnorm
  k_rms2<<<RROWS, 256>>>();

  // 7) H = gelu(G2n @ Wdown.T + bias)
  gemm_k<3,1,0,0><<<dim3(8,32,1), 256>>>(pG2n, Wdown, nullptr, nullptr, pH,
      RROWS, INNER, KK, 0, 0, 0, mbias, nullptr, nullptr, nullptr);

  // 8) OutU = H @ Wup.T
  gemm_k<0,1,0,0><<<dim3(4,32,1), 256>>>(pH, Wup, nullptr, nullptr, pOutU,
      RROWS, KK, INNER, 0, 0, 0, nullptr, nullptr, nullptr, nullptr);

  // 9) fused entropy + delta + exact top-128 + masked write
  cudaFuncSetAttribute(k_final, cudaFuncAttributeMaxDynamicSharedMemorySize, VVV*4);
  k_final<<<RROWS, NTB, VVV*4>>>(x, pOutU, widx, wscale, out);
}